// round 1
// baseline (speedup 1.0000x reference)
#include <cuda_runtime.h>
#include <cstdint>
#include <math.h>

#define D_DIM   1024
#define T_DIM   50
#define STRIDEQ 10
#define NUM_POS 16
#define MAX_B   4096
#define MAX_KP  13108   /* ceil(131072/10) */

// ---- device scratch (static; no allocations allowed) ----
__device__ float              g_inv_k[MAX_KP];
__device__ unsigned long long g_q0[MAX_KP];
__device__ unsigned long long g_q1[MAX_KP];
__device__ float              g_inv_q[MAX_B];
__device__ unsigned long long g_a0[MAX_B];
__device__ unsigned long long g_a1[MAX_B];
__device__ int                g_sel[MAX_B * NUM_POS];
__device__ int                g_cnt[MAX_B];
__device__ float              g_per[MAX_B];

// ------------------------------------------------------------------
// Kernel 1: per strided queue row -> 1/(||row||+eps) and packed labels
// One warp per k' row.
// ------------------------------------------------------------------
__global__ void prep_queue(const float* __restrict__ qf,
                           const int*   __restrict__ qlab, int Kp) {
    int warp = (blockIdx.x * blockDim.x + threadIdx.x) >> 5;
    int lane = threadIdx.x & 31;
    if (warp >= Kp) return;
    long long row = (long long)warp * STRIDEQ;

    const float4* p = (const float4*)(qf + row * D_DIM);
    float ss = 0.f;
#pragma unroll
    for (int i = 0; i < D_DIM / 4 / 32; i++) {
        float4 v = p[lane + i * 32];
        ss += v.x * v.x + v.y * v.y + v.z * v.z + v.w * v.w;
    }
#pragma unroll
    for (int o = 16; o; o >>= 1) ss += __shfl_xor_sync(0xffffffffu, ss, o);
    float inv = 1.0f / (sqrtf(ss) + 1e-8f);

    const int* lp = qlab + row * (T_DIM * 2);
    int l0a = lp[lane * 2];
    int l1a = lp[lane * 2 + 1];
    int t1 = 32 + lane;
    int l0b = 0, l1b = 0;
    if (t1 < T_DIM) { l0b = lp[t1 * 2]; l1b = lp[t1 * 2 + 1]; }
    unsigned b0lo = __ballot_sync(0xffffffffu, l0a != 0);
    unsigned b1lo = __ballot_sync(0xffffffffu, l1a != 0);
    unsigned b0hi = __ballot_sync(0xffffffffu, l0b != 0);
    unsigned b1hi = __ballot_sync(0xffffffffu, l1b != 0);
    if (lane == 0) {
        g_inv_k[warp] = inv;
        g_q0[warp] = (unsigned long long)b0lo | ((unsigned long long)b0hi << 32);
        g_q1[warp] = (unsigned long long)b1lo | ((unsigned long long)b1hi << 32);
    }
}

// ------------------------------------------------------------------
// Kernel 2: per anchor row -> 1/(||row||+eps) and packed labels
// ------------------------------------------------------------------
__global__ void prep_anchor(const float* __restrict__ xq,
                            const int*   __restrict__ xlab, int B) {
    int warp = (blockIdx.x * blockDim.x + threadIdx.x) >> 5;
    int lane = threadIdx.x & 31;
    if (warp >= B) return;

    const float4* p = (const float4*)(xq + (long long)warp * D_DIM);
    float ss = 0.f;
#pragma unroll
    for (int i = 0; i < D_DIM / 4 / 32; i++) {
        float4 v = p[lane + i * 32];
        ss += v.x * v.x + v.y * v.y + v.z * v.z + v.w * v.w;
    }
#pragma unroll
    for (int o = 16; o; o >>= 1) ss += __shfl_xor_sync(0xffffffffu, ss, o);
    float inv = 1.0f / (sqrtf(ss) + 1e-8f);

    const int* lp = xlab + (long long)warp * (T_DIM * 2);
    int l0a = lp[lane * 2];
    int l1a = lp[lane * 2 + 1];
    int t1 = 32 + lane;
    int l0b = 0, l1b = 0;
    if (t1 < T_DIM) { l0b = lp[t1 * 2]; l1b = lp[t1 * 2 + 1]; }
    unsigned b0lo = __ballot_sync(0xffffffffu, l0a != 0);
    unsigned b1lo = __ballot_sync(0xffffffffu, l1a != 0);
    unsigned b0hi = __ballot_sync(0xffffffffu, l0b != 0);
    unsigned b1hi = __ballot_sync(0xffffffffu, l1b != 0);
    if (lane == 0) {
        g_inv_q[warp] = inv;
        g_a0[warp] = (unsigned long long)b0lo | ((unsigned long long)b0hi << 32);
        g_a1[warp] = (unsigned long long)b1lo | ((unsigned long long)b1hi << 32);
    }
}

// ------------------------------------------------------------------
// Kernel 3: per anchor, scan k' in order; mask via popcount table;
// record first <=16 valid indices and count (early exit at 16).
// One warp per anchor.
// ------------------------------------------------------------------
__global__ void select_pos(int B, int Kp) {
    int warp = (blockIdx.x * blockDim.x + threadIdx.x) >> 5;
    int lane = threadIdx.x & 31;
    if (warp >= B) return;

    unsigned long long a0 = g_a0[warp];
    unsigned long long a1 = g_a1[warp];
    unsigned long long da = a0 & a1;       // diag states (1,1)
    unsigned long long xa = a0 ^ a1;       // axis states (1,0)/(0,1)

    // fp32 constants exactly as reference computes them
    float c  = 1.0f / (sqrtf(2.0f) + 1e-8f);  // axis . diag
    float cc = c * c;
    float d2 = cc + cc;                        // diag . diag

    int total = 0;
    for (int kb = 0; kb < Kp; kb += 32) {
        int k = kb + lane;
        bool pred = false;
        if (k < Kp) {
            unsigned long long q0 = g_q0[k];
            unsigned long long q1 = g_q1[k];
            unsigned long long dq = q0 & q1;
            unsigned long long xq = q0 ^ q1;
            unsigned long long m1  = (xa & xq) & ((a0 & q0) | (a1 & q1));
            unsigned long long mc  = (da & xq) | (xa & dq);
            unsigned long long mdd = da & dq;
            float s = (float)__popcll(m1)
                    + (float)__popcll(mc)  * c
                    + (float)__popcll(mdd) * d2;
            pred = ((s / 50.0f) >= 0.5f);
        }
        unsigned m = __ballot_sync(0xffffffffu, pred);
        if (pred) {
            int rank = total + __popc(m & ((1u << lane) - 1u));
            if (rank < NUM_POS) g_sel[warp * NUM_POS + rank] = k;
        }
        total += __popc(m);
        if (total >= NUM_POS) break;
    }
    if (lane == 0) g_cnt[warp] = (total < NUM_POS) ? total : NUM_POS;
}

// ------------------------------------------------------------------
// Kernel 4: per anchor, dot products with selected rows + loss.
// One block (16 warps) per anchor; warp w handles selected index w.
// ------------------------------------------------------------------
__global__ void compute_loss(const float* __restrict__ xq,
                             const float* __restrict__ qf) {
    int b = blockIdx.x;
    int w = threadIdx.x >> 5;
    int lane = threadIdx.x & 31;
    __shared__ float sloss[NUM_POS];

    int cnt = g_cnt[b];
    float loss = 0.f;
    if (w < cnt) {
        int kp = g_sel[b * NUM_POS + w];
        long long row = (long long)kp * STRIDEQ;
        const float4* pa = (const float4*)(xq + (long long)b * D_DIM);
        const float4* pk = (const float4*)(qf + row * D_DIM);
        float dot = 0.f;
#pragma unroll
        for (int i = 0; i < D_DIM / 4 / 32; i++) {
            float4 a  = pa[lane + i * 32];
            float4 kk = pk[lane + i * 32];
            dot += a.x * kk.x + a.y * kk.y + a.z * kk.z + a.w * kk.w;
        }
#pragma unroll
        for (int o = 16; o; o >>= 1) dot += __shfl_xor_sync(0xffffffffu, dot, o);
        float s = dot * g_inv_q[b] * g_inv_k[kp] * 2.0f;  // / TEMPERATURE(0.5)
        // loss = -log_sigmoid(s) = softplus(-s) (stable form)
        float z = -s;
        loss = fmaxf(z, 0.f) + log1pf(expf(-fabsf(z)));
    }
    if (lane == 0) sloss[w] = loss;
    __syncthreads();
    if (threadIdx.x == 0) {
        float sum = 0.f;
#pragma unroll
        for (int i = 0; i < NUM_POS; i++) sum += sloss[i];
        g_per[b] = (cnt > 0) ? (sum / (float)cnt) : 0.f;
    }
}

// ------------------------------------------------------------------
// Kernel 5: deterministic mean over anchors (double accumulation).
// ------------------------------------------------------------------
__global__ void reduce_mean(float* __restrict__ out, int B) {
    __shared__ double sh[256];
    double acc = 0.0;
    for (int i = threadIdx.x; i < B; i += 256) acc += (double)g_per[i];
    sh[threadIdx.x] = acc;
    __syncthreads();
    for (int s = 128; s; s >>= 1) {
        if (threadIdx.x < s) sh[threadIdx.x] += sh[threadIdx.x + s];
        __syncthreads();
    }
    if (threadIdx.x == 0) out[0] = (float)(sh[0] / (double)B);
}

extern "C" void kernel_launch(void* const* d_in, const int* in_sizes, int n_in,
                              void* d_out, int out_size) {
    const float* xq   = (const float*)d_in[0];
    const int*   xlab = (const int*)  d_in[1];
    const float* qf   = (const float*)d_in[2];
    const int*   qlab = (const int*)  d_in[3];

    int B  = in_sizes[0] / D_DIM;                 // 4096
    int K  = in_sizes[2] / D_DIM;                 // 131072
    int Kp = (K + STRIDEQ - 1) / STRIDEQ;         // 13108

    prep_queue <<<(Kp + 3) / 4, 128>>>(qf, qlab, Kp);
    prep_anchor<<<(B  + 3) / 4, 128>>>(xq, xlab, B);
    select_pos <<<(B  + 3) / 4, 128>>>(B, Kp);
    compute_loss<<<B, NUM_POS * 32>>>(xq, qf);
    reduce_mean<<<1, 256>>>((float*)d_out, B);
}